// round 10
// baseline (speedup 1.0000x reference)
#include <cuda_runtime.h>

// ---------------------------------------------------------------------------
// Fused Conv2d(1->16,5x5,pad2) + BatchNorm(inference) + ReLU + MaxPool2x2
// Input  x: [128, 1, 224, 224] f32  ->  Output [128, 16, 112, 112] f32
//
// R6 changes vs R5 (124us, fma=60%, occ=23%, alu=21%):
//  - __launch_bounds__(256,2): guarantee 2 CTAs/SM (regs<=128) -> 4 warps/SMSP
//  - weights pre-packed as duplicated f32x2 in the fuse kernel; smem holds
//    64-bit packed weights -> single LDS.64, no per-weight mov.b64 packing.
// ---------------------------------------------------------------------------

__device__ unsigned long long g_wp[16 * 25];  // BN-folded weights, packed {w,w}
__device__ unsigned long long g_bp[16];       // BN-folded bias, packed {b,b}

__global__ void fuse_params_kernel(const float* __restrict__ w,
                                   const float* __restrict__ b,
                                   const float* __restrict__ gamma,
                                   const float* __restrict__ beta,
                                   const float* __restrict__ mean,
                                   const float* __restrict__ var) {
    int c = threadIdx.x;
    if (c < 16) {
        float s = gamma[c] * rsqrtf(var[c] + 1e-5f);
        float bf = b[c] * s + beta[c] - mean[c] * s;
        unsigned long long bp;
        asm("mov.b64 %0, {%1, %1};" : "=l"(bp) : "f"(bf));
        g_bp[c] = bp;
#pragma unroll
        for (int k = 0; k < 25; k++) {
            float wf = w[c * 25 + k] * s;
            unsigned long long wp;
            asm("mov.b64 %0, {%1, %1};" : "=l"(wp) : "f"(wf));
            g_wp[c * 25 + k] = wp;
        }
    }
}

__device__ __forceinline__ unsigned long long pk2(float lo, float hi) {
    unsigned long long r;
    asm("mov.b64 %0, {%1, %2};" : "=l"(r) : "f"(lo), "f"(hi));
    return r;
}
__device__ __forceinline__ void upk2(unsigned long long v, float& lo, float& hi) {
    asm("mov.b64 {%0, %1}, %2;" : "=f"(lo), "=f"(hi) : "l"(v));
}
__device__ __forceinline__ unsigned long long fma2(unsigned long long a,
                                                   unsigned long long b,
                                                   unsigned long long c) {
    unsigned long long d;
    asm("fma.rn.f32x2 %0, %1, %2, %3;" : "=l"(d) : "l"(a), "l"(b), "l"(c));
    return d;
}

// Grid: 1568 blocks x 256 threads = 401408 threads = 128 images * 56*56 quads.
// Each quad = pooled 2x2 block at (2*qy, 2*qx), i.e. pre-pool rows 4qy..4qy+3.
__global__ __launch_bounds__(256, 2)
void conv_bn_relu_pool_kernel(const float* __restrict__ x,
                              float* __restrict__ out) {
    __shared__ unsigned long long sw[16 * 25];
    __shared__ unsigned long long sb[16];
    int t = threadIdx.x;
    for (int i = t; i < 16 * 25; i += 256) sw[i] = g_wp[i];
    if (t < 16) sb[t] = g_bp[t];
    __syncthreads();

    int tid  = blockIdx.x * 256 + t;
    int bimg = tid / 3136;            // 3136 = 56*56 quads per image
    int rem  = tid - bimg * 3136;
    int qy   = rem / 56;
    int qx   = rem - qy * 56;

    const float* xb = x + bimg * (224 * 224);
    int r0 = 4 * qy - 2;   // top row of 8x8 input window (pad=2)
    int c0 = 4 * qx - 2;   // left col

    // --- load 8x8 input window with zero padding (shared by all 16 channels)
    float xin[8][8];
#pragma unroll
    for (int i = 0; i < 8; i++) {
        int r = r0 + i;
        bool rv = ((unsigned)r < 224u);
        const float* xr = xb + r * 224;
#pragma unroll
        for (int j = 0; j < 8; j++) {
            int cc = c0 + j;
            bool v = rv && ((unsigned)cc < 224u);
            xin[i][j] = v ? __ldg(xr + cc) : 0.0f;
        }
    }

    // --- pack pairs: slots 0..3 = even alignment (0,1)(2,3)(4,5)(6,7)
    //                 slots 4..6 = odd alignment  (1,2)(3,4)(5,6)
    unsigned long long P[8][7];
#pragma unroll
    for (int i = 0; i < 8; i++) {
#pragma unroll
        for (int k = 0; k < 4; k++) P[i][k] = pk2(xin[i][2 * k], xin[i][2 * k + 1]);
#pragma unroll
        for (int k = 0; k < 3; k++) P[i][4 + k] = pk2(xin[i][2 * k + 1], xin[i][2 * k + 2]);
    }

    float* ob = out + ((bimg * 16) * 112 + 2 * qy) * 112 + 2 * qx;

#pragma unroll 1
    for (int c = 0; c < 16; c++) {
        const unsigned long long* wc = sw + c * 25;
        unsigned long long bp = sb[c];
        unsigned long long acc[4][2];
#pragma unroll
        for (int o = 0; o < 4; o++) { acc[o][0] = bp; acc[o][1] = bp; }

#pragma unroll
        for (int kr = 0; kr < 5; kr++) {
#pragma unroll
            for (int kc = 0; kc < 5; kc++) {
                unsigned long long wp = wc[kr * 5 + kc];   // LDS.64, pre-packed
                // pair slot for output cols (0,1); +1 gives cols (2,3)
                int pi = (kc & 1) ? (4 + (kc >> 1)) : (kc >> 1);
#pragma unroll
                for (int o = 0; o < 4; o++) {
                    acc[o][0] = fma2(P[o + kr][pi],     wp, acc[o][0]);
                    acc[o][1] = fma2(P[o + kr][pi + 1], wp, acc[o][1]);
                }
            }
        }

        // --- ReLU + 2x2 max pool (relu commutes with max)
        float a[4][4];
#pragma unroll
        for (int o = 0; o < 4; o++) {
            upk2(acc[o][0], a[o][0], a[o][1]);
            upk2(acc[o][1], a[o][2], a[o][3]);
        }
        float2 s0, s1;
        s0.x = fmaxf(fmaxf(fmaxf(a[0][0], a[0][1]), fmaxf(a[1][0], a[1][1])), 0.0f);
        s0.y = fmaxf(fmaxf(fmaxf(a[0][2], a[0][3]), fmaxf(a[1][2], a[1][3])), 0.0f);
        s1.x = fmaxf(fmaxf(fmaxf(a[2][0], a[2][1]), fmaxf(a[3][0], a[3][1])), 0.0f);
        s1.y = fmaxf(fmaxf(fmaxf(a[2][2], a[2][3]), fmaxf(a[3][2], a[3][3])), 0.0f);

        *reinterpret_cast<float2*>(ob)       = s0;  // row 2qy
        *reinterpret_cast<float2*>(ob + 112) = s1;  // row 2qy+1
        ob += 112 * 112;                            // next channel plane
    }
}

extern "C" void kernel_launch(void* const* d_in, const int* in_sizes, int n_in,
                              void* d_out, int out_size) {
    const float* x     = (const float*)d_in[0];
    const float* w     = (const float*)d_in[1];
    const float* bias  = (const float*)d_in[2];
    const float* gamma = (const float*)d_in[3];
    const float* beta  = (const float*)d_in[4];
    const float* mean  = (const float*)d_in[5];
    const float* var   = (const float*)d_in[6];
    float* out = (float*)d_out;

    fuse_params_kernel<<<1, 32>>>(w, bias, gamma, beta, mean, var);
    conv_bn_relu_pool_kernel<<<1568, 256>>>(x, out);
}

// round 11
// speedup vs baseline: 1.0055x; 1.0055x over previous
#include <cuda_runtime.h>

// ---------------------------------------------------------------------------
// Fused Conv2d(1->16,5x5,pad2) + BatchNorm(inference) + ReLU + MaxPool2x2
// Input  x: [128, 1, 224, 224] f32  ->  Output [128, 16, 112, 112] f32
//
// R6 changes vs R5 (124us, fma=60%, occ=23%, alu=21%):
//  - __launch_bounds__(256,2): guarantee 2 CTAs/SM (regs<=128) -> 4 warps/SMSP
//  - weights pre-packed as duplicated f32x2 in the fuse kernel; smem holds
//    64-bit packed weights -> single LDS.64, no per-weight mov.b64 packing.
// ---------------------------------------------------------------------------

__device__ unsigned long long g_wp[16 * 25];  // BN-folded weights, packed {w,w}
__device__ unsigned long long g_bp[16];       // BN-folded bias, packed {b,b}

__global__ void fuse_params_kernel(const float* __restrict__ w,
                                   const float* __restrict__ b,
                                   const float* __restrict__ gamma,
                                   const float* __restrict__ beta,
                                   const float* __restrict__ mean,
                                   const float* __restrict__ var) {
    int c = threadIdx.x;
    if (c < 16) {
        float s = gamma[c] * rsqrtf(var[c] + 1e-5f);
        float bf = b[c] * s + beta[c] - mean[c] * s;
        unsigned long long bp;
        asm("mov.b64 %0, {%1, %1};" : "=l"(bp) : "f"(bf));
        g_bp[c] = bp;
#pragma unroll
        for (int k = 0; k < 25; k++) {
            float wf = w[c * 25 + k] * s;
            unsigned long long wp;
            asm("mov.b64 %0, {%1, %1};" : "=l"(wp) : "f"(wf));
            g_wp[c * 25 + k] = wp;
        }
    }
}

__device__ __forceinline__ unsigned long long pk2(float lo, float hi) {
    unsigned long long r;
    asm("mov.b64 %0, {%1, %2};" : "=l"(r) : "f"(lo), "f"(hi));
    return r;
}
__device__ __forceinline__ void upk2(unsigned long long v, float& lo, float& hi) {
    asm("mov.b64 {%0, %1}, %2;" : "=f"(lo), "=f"(hi) : "l"(v));
}
__device__ __forceinline__ unsigned long long fma2(unsigned long long a,
                                                   unsigned long long b,
                                                   unsigned long long c) {
    unsigned long long d;
    asm("fma.rn.f32x2 %0, %1, %2, %3;" : "=l"(d) : "l"(a), "l"(b), "l"(c));
    return d;
}

// Grid: 1568 blocks x 256 threads = 401408 threads = 128 images * 56*56 quads.
// Each quad = pooled 2x2 block at (2*qy, 2*qx), i.e. pre-pool rows 4qy..4qy+3.
__global__ __launch_bounds__(256, 2)
void conv_bn_relu_pool_kernel(const float* __restrict__ x,
                              float* __restrict__ out) {
    __shared__ unsigned long long sw[16 * 25];
    __shared__ unsigned long long sb[16];
    int t = threadIdx.x;
    for (int i = t; i < 16 * 25; i += 256) sw[i] = g_wp[i];
    if (t < 16) sb[t] = g_bp[t];
    __syncthreads();

    int tid  = blockIdx.x * 256 + t;
    int bimg = tid / 3136;            // 3136 = 56*56 quads per image
    int rem  = tid - bimg * 3136;
    int qy   = rem / 56;
    int qx   = rem - qy * 56;

    const float* xb = x + bimg * (224 * 224);
    int r0 = 4 * qy - 2;   // top row of 8x8 input window (pad=2)
    int c0 = 4 * qx - 2;   // left col

    // --- load 8x8 input window with zero padding (shared by all 16 channels)
    float xin[8][8];
#pragma unroll
    for (int i = 0; i < 8; i++) {
        int r = r0 + i;
        bool rv = ((unsigned)r < 224u);
        const float* xr = xb + r * 224;
#pragma unroll
        for (int j = 0; j < 8; j++) {
            int cc = c0 + j;
            bool v = rv && ((unsigned)cc < 224u);
            xin[i][j] = v ? __ldg(xr + cc) : 0.0f;
        }
    }

    // --- pack pairs: slots 0..3 = even alignment (0,1)(2,3)(4,5)(6,7)
    //                 slots 4..6 = odd alignment  (1,2)(3,4)(5,6)
    unsigned long long P[8][7];
#pragma unroll
    for (int i = 0; i < 8; i++) {
#pragma unroll
        for (int k = 0; k < 4; k++) P[i][k] = pk2(xin[i][2 * k], xin[i][2 * k + 1]);
#pragma unroll
        for (int k = 0; k < 3; k++) P[i][4 + k] = pk2(xin[i][2 * k + 1], xin[i][2 * k + 2]);
    }

    float* ob = out + ((bimg * 16) * 112 + 2 * qy) * 112 + 2 * qx;

#pragma unroll 1
    for (int c = 0; c < 16; c++) {
        const unsigned long long* wc = sw + c * 25;
        unsigned long long bp = sb[c];
        unsigned long long acc[4][2];
#pragma unroll
        for (int o = 0; o < 4; o++) { acc[o][0] = bp; acc[o][1] = bp; }

#pragma unroll
        for (int kr = 0; kr < 5; kr++) {
#pragma unroll
            for (int kc = 0; kc < 5; kc++) {
                unsigned long long wp = wc[kr * 5 + kc];   // LDS.64, pre-packed
                // pair slot for output cols (0,1); +1 gives cols (2,3)
                int pi = (kc & 1) ? (4 + (kc >> 1)) : (kc >> 1);
#pragma unroll
                for (int o = 0; o < 4; o++) {
                    acc[o][0] = fma2(P[o + kr][pi],     wp, acc[o][0]);
                    acc[o][1] = fma2(P[o + kr][pi + 1], wp, acc[o][1]);
                }
            }
        }

        // --- ReLU + 2x2 max pool (relu commutes with max)
        float a[4][4];
#pragma unroll
        for (int o = 0; o < 4; o++) {
            upk2(acc[o][0], a[o][0], a[o][1]);
            upk2(acc[o][1], a[o][2], a[o][3]);
        }
        float2 s0, s1;
        s0.x = fmaxf(fmaxf(fmaxf(a[0][0], a[0][1]), fmaxf(a[1][0], a[1][1])), 0.0f);
        s0.y = fmaxf(fmaxf(fmaxf(a[0][2], a[0][3]), fmaxf(a[1][2], a[1][3])), 0.0f);
        s1.x = fmaxf(fmaxf(fmaxf(a[2][0], a[2][1]), fmaxf(a[3][0], a[3][1])), 0.0f);
        s1.y = fmaxf(fmaxf(fmaxf(a[2][2], a[2][3]), fmaxf(a[3][2], a[3][3])), 0.0f);

        *reinterpret_cast<float2*>(ob)       = s0;  // row 2qy
        *reinterpret_cast<float2*>(ob + 112) = s1;  // row 2qy+1
        ob += 112 * 112;                            // next channel plane
    }
}

extern "C" void kernel_launch(void* const* d_in, const int* in_sizes, int n_in,
                              void* d_out, int out_size) {
    const float* x     = (const float*)d_in[0];
    const float* w     = (const float*)d_in[1];
    const float* bias  = (const float*)d_in[2];
    const float* gamma = (const float*)d_in[3];
    const float* beta  = (const float*)d_in[4];
    const float* mean  = (const float*)d_in[5];
    const float* var   = (const float*)d_in[6];
    float* out = (float*)d_out;

    fuse_params_kernel<<<1, 32>>>(w, bias, gamma, beta, mean, var);
    conv_bn_relu_pool_kernel<<<1568, 256>>>(x, out);
}

// round 12
// speedup vs baseline: 1.0564x; 1.0505x over previous
#include <cuda_runtime.h>

// ---------------------------------------------------------------------------
// Fused Conv2d(1->16,5x5,pad2) + BatchNorm(inference) + ReLU + MaxPool2x2
// Input  x: [128, 1, 224, 224] f32  ->  Output [128, 16, 112, 112] f32
//
// R11: register-pressure rewrite.
//  - Input window kept ONLY as even-aligned f32x2 pairs (32 pairs = 64 regs),
//    loaded directly with predicated LDG.64 (c0 is even -> 8B aligned).
//  - Parity-split accumulators: even-kc taps -> even-aligned output pairs,
//    odd-kc taps -> odd-aligned output pairs; combined with scalar FADDs.
//    Eliminates the 112-register dual-alignment array -> no spills.
// ---------------------------------------------------------------------------

__device__ unsigned long long g_wp[16 * 25];  // BN-folded weights, packed {w,w}
__device__ unsigned long long g_bp[16];       // BN-folded bias, packed {b,b}

__global__ void fuse_params_kernel(const float* __restrict__ w,
                                   const float* __restrict__ b,
                                   const float* __restrict__ gamma,
                                   const float* __restrict__ beta,
                                   const float* __restrict__ mean,
                                   const float* __restrict__ var) {
    int c = threadIdx.x;
    if (c < 16) {
        float s = gamma[c] * rsqrtf(var[c] + 1e-5f);
        float bf = b[c] * s + beta[c] - mean[c] * s;
        unsigned long long bp;
        asm("mov.b64 %0, {%1, %1};" : "=l"(bp) : "f"(bf));
        g_bp[c] = bp;
#pragma unroll
        for (int k = 0; k < 25; k++) {
            float wf = w[c * 25 + k] * s;
            unsigned long long wp;
            asm("mov.b64 %0, {%1, %1};" : "=l"(wp) : "f"(wf));
            g_wp[c * 25 + k] = wp;
        }
    }
}

__device__ __forceinline__ void upk2(unsigned long long v, float& lo, float& hi) {
    asm("mov.b64 {%0, %1}, %2;" : "=f"(lo), "=f"(hi) : "l"(v));
}
__device__ __forceinline__ unsigned long long fma2(unsigned long long a,
                                                   unsigned long long b,
                                                   unsigned long long c) {
    unsigned long long d;
    asm("fma.rn.f32x2 %0, %1, %2, %3;" : "=l"(d) : "l"(a), "l"(b), "l"(c));
    return d;
}

// Grid: 1568 blocks x 256 threads = 401408 threads = 128 images * 56*56 quads.
// Each quad = pooled 2x2 block at (2*qy, 2*qx), i.e. pre-pool rows 4qy..4qy+3,
// cols 4qx..4qx+3. Input window rows r0..r0+7, cols c0..c0+7 (r0=4qy-2 etc).
__global__ __launch_bounds__(256, 2)
void conv_bn_relu_pool_kernel(const float* __restrict__ x,
                              float* __restrict__ out) {
    __shared__ unsigned long long sw[16 * 25];
    __shared__ unsigned long long sb[16];
    int t = threadIdx.x;
    for (int i = t; i < 16 * 25; i += 256) sw[i] = g_wp[i];
    if (t < 16) sb[t] = g_bp[t];
    __syncthreads();

    int tid  = blockIdx.x * 256 + t;
    int bimg = tid / 3136;            // 3136 = 56*56 quads per image
    int rem  = tid - bimg * 3136;
    int qy   = rem / 56;
    int qx   = rem - qy * 56;

    const float* xb = x + bimg * (224 * 224);
    int r0 = 4 * qy - 2;   // top row of 8x8 window (pad=2)
    int c0 = 4 * qx - 2;   // left col (EVEN -> 8B-aligned pairs)

    // --- load 8x4 even-aligned f32 pairs directly with predicated LDG.64.
    // Pair k covers cols c0+2k, c0+2k+1. Padding is pair-granular: both lanes
    // in range iff (unsigned)(c0+2k) < 224 (cols even, 224 even).
    bool colOK[4];
#pragma unroll
    for (int k = 0; k < 4; k++) colOK[k] = ((unsigned)(c0 + 2 * k) < 224u);

    unsigned long long P[8][4];
#pragma unroll
    for (int i = 0; i < 8; i++) {
        int r = r0 + i;
        bool rv = ((unsigned)r < 224u);
        const float* base = xb + r * 224 + c0;
#pragma unroll
        for (int k = 0; k < 4; k++) {
            P[i][k] = (rv && colOK[k])
                ? __ldg(reinterpret_cast<const unsigned long long*>(base + 2 * k))
                : 0ull;
        }
    }

    float* ob = out + ((bimg * 16) * 112 + 2 * qy) * 112 + 2 * qx;

#pragma unroll 1
    for (int c = 0; c < 16; c++) {
        const unsigned long long* wc = sw + c * 25;

        // evenAcc[o][jp] = output pair (cols 2jp, 2jp+1), row o  (bias folded in)
        // oddAcc[o][s]   = output pair (cols 2s-1, 2s), row o    (lanes -1 & 4 garbage)
        unsigned long long eA[4][2];
        unsigned long long oA[4][3];
        unsigned long long bp = sb[c];
#pragma unroll
        for (int o = 0; o < 4; o++) {
            eA[o][0] = bp; eA[o][1] = bp;
            oA[o][0] = 0ull; oA[o][1] = 0ull; oA[o][2] = 0ull;
        }

#pragma unroll
        for (int kr = 0; kr < 5; kr++) {
            // even kc: w[kc] * (x[j+kc], x[j+1+kc]) -> even pair (j+kc)/2 = jp + kc/2
#pragma unroll
            for (int kch = 0; kch < 3; kch++) {          // kc = 0,2,4
                int kc = 2 * kch;
                unsigned long long wp = wc[kr * 5 + kc];
#pragma unroll
                for (int o = 0; o < 4; o++) {
#pragma unroll
                    for (int jp = 0; jp < 2; jp++)
                        eA[o][jp] = fma2(P[o + kr][jp + kch], wp, eA[o][jp]);
                }
            }
            // odd kc: pair m = kc + 2s - 1 (even) feeds output pair (2s-1, 2s)
            //   kc=1 -> P index s ; kc=3 -> P index s+1
#pragma unroll
            for (int kco = 0; kco < 2; kco++) {          // kc = 1,3
                int kc = 2 * kco + 1;
                unsigned long long wp = wc[kr * 5 + kc];
#pragma unroll
                for (int o = 0; o < 4; o++) {
#pragma unroll
                    for (int s = 0; s < 3; s++)
                        oA[o][s] = fma2(P[o + kr][s + kco], wp, oA[o][s]);
                }
            }
        }

        // --- combine parities, ReLU + 2x2 max pool (relu commutes with max)
        float rowv[4][4];
#pragma unroll
        for (int o = 0; o < 4; o++) {
            float e0, e1, e2, e3, g0, d0, d1, d2, d3, g1;
            upk2(eA[o][0], e0, e1);
            upk2(eA[o][1], e2, e3);
            upk2(oA[o][0], g0, d0);   // (out -1, out 0)
            upk2(oA[o][1], d1, d2);   // (out 1,  out 2)
            upk2(oA[o][2], d3, g1);   // (out 3,  out 4)
            rowv[o][0] = e0 + d0;
            rowv[o][1] = e1 + d1;
            rowv[o][2] = e2 + d2;
            rowv[o][3] = e3 + d3;
        }
        float2 s0, s1;
        s0.x = fmaxf(fmaxf(fmaxf(rowv[0][0], rowv[0][1]), fmaxf(rowv[1][0], rowv[1][1])), 0.0f);
        s0.y = fmaxf(fmaxf(fmaxf(rowv[0][2], rowv[0][3]), fmaxf(rowv[1][2], rowv[1][3])), 0.0f);
        s1.x = fmaxf(fmaxf(fmaxf(rowv[2][0], rowv[2][1]), fmaxf(rowv[3][0], rowv[3][1])), 0.0f);
        s1.y = fmaxf(fmaxf(fmaxf(rowv[2][2], rowv[2][3]), fmaxf(rowv[3][2], rowv[3][3])), 0.0f);

        *reinterpret_cast<float2*>(ob)       = s0;  // row 2qy
        *reinterpret_cast<float2*>(ob + 112) = s1;  // row 2qy+1
        ob += 112 * 112;                            // next channel plane
    }
}

extern "C" void kernel_launch(void* const* d_in, const int* in_sizes, int n_in,
                              void* d_out, int out_size) {
    const float* x     = (const float*)d_in[0];
    const float* w     = (const float*)d_in[1];
    const float* bias  = (const float*)d_in[2];
    const float* gamma = (const float*)d_in[3];
    const float* beta  = (const float*)d_in[4];
    const float* mean  = (const float*)d_in[5];
    const float* var   = (const float*)d_in[6];
    float* out = (float*)d_out;

    fuse_params_kernel<<<1, 32>>>(w, bias, gamma, beta, mean, var);
    conv_bn_relu_pool_kernel<<<1568, 256>>>(x, out);
}